// round 13
// baseline (speedup 1.0000x reference)
#include <cuda_runtime.h>
#include <math.h>

#define BB 16
#define NN 300000
#define NV 75000
#define NBLK 37
#define PRE 2000
#define POST 1000
#define CANDMAX 4096
#define MASKW 32
#define STAGE 1024

typedef unsigned long long ull;

__device__ unsigned g_hist[BB][2048];   // zeroed by k_scan for next replay
__device__ int g_cut[BB];
__device__ unsigned g_ccount[BB];       // zeroed by k_scan for next replay
__device__ ull g_cand[BB][CANDMAX];
__device__ float4 g_boxes[BB][PRE];
__device__ float g_area[BB][PRE];
__device__ int g_nvalid[BB];
__device__ ull g_mask[BB][PRE][MASKW];

__device__ __forceinline__ unsigned keyf(float f) {
    unsigned u = __float_as_uint(f);
    return u ^ ((u >> 31) ? 0xFFFFFFFFu : 0x80000000u);
}

__device__ __forceinline__ unsigned smaddr(const void* p) {
    return (unsigned)__cvta_generic_to_shared(p);
}
#define CP8(dst, src) asm volatile("cp.async.ca.shared.global [%0], [%1], 8;" :: "r"(dst), "l"(src))
#define CPCOMMIT() asm volatile("cp.async.commit_group;")
#define CPWAIT2() asm volatile("cp.async.wait_group 2;")
#define CPWAITALL() asm volatile("cp.async.wait_all;")

__global__ void __launch_bounds__(256) k_hist(const float* __restrict__ cls) {
    __shared__ unsigned sh[2048];
    int b = blockIdx.y;
    int t = threadIdx.x;
    for (int i = t; i < 2048; i += 256) sh[i] = 0u;
    __syncthreads();
    const float4* __restrict__ p = (const float4*)(cls + (size_t)b * NN);
    int base = blockIdx.x * 2048;
    if (base + 2048 <= NV) {
        float4 v[8];
#pragma unroll
        for (int k = 0; k < 8; k++) v[k] = p[base + t + 256 * k];
#pragma unroll
        for (int k = 0; k < 8; k++) {
            unsigned kk[4] = {keyf(v[k].x), keyf(v[k].y), keyf(v[k].z), keyf(v[k].w)};
#pragma unroll
            for (int q = 0; q < 4; q++)
                if (kk[q] >= 0x80000000u) atomicAdd(&sh[(kk[q] >> 20) - 2048], 1u);
        }
    } else {
        for (int k = 0; k < 8; k++) {
            int id = base + t + 256 * k;
            if (id < NV) {
                float4 v = p[id];
                unsigned kk[4] = {keyf(v.x), keyf(v.y), keyf(v.z), keyf(v.w)};
#pragma unroll
                for (int q = 0; q < 4; q++)
                    if (kk[q] >= 0x80000000u) atomicAdd(&sh[(kk[q] >> 20) - 2048], 1u);
            }
        }
    }
    __syncthreads();
    for (int i = t; i < 2048; i += 256) {
        unsigned c = sh[i];
        if (c) atomicAdd(&g_hist[b][i], c);
    }
}

__global__ void __launch_bounds__(256) k_compact(const float* __restrict__ cls) {
    __shared__ ull stage[STAGE];
    __shared__ unsigned hist4[4096];   // cold path only
    __shared__ unsigned wsum[8];
    __shared__ unsigned wsuf[9];
    __shared__ int s_cut;
    __shared__ unsigned s_cnt, s_base;
    int b = blockIdx.y;
    int t = threadIdx.x;
    int lane = t & 31, wid = t >> 5;
    const float4* __restrict__ p = (const float4*)(cls + (size_t)b * NN);
    unsigned hv[8];
    unsigned s = 0;
#pragma unroll
    for (int q = 0; q < 8; q++) { hv[q] = g_hist[b][t * 8 + q]; s += hv[q]; }
    unsigned v = s;
#pragma unroll
    for (int o = 1; o < 32; o <<= 1) {
        unsigned t2 = __shfl_down_sync(0xffffffffu, v, o);
        if (lane + o < 32) v += t2;
    }
    if (lane == 0) wsum[wid] = v;
    __syncthreads();
    if (t < 8) {
        unsigned x = 0;
        for (int j = t; j < 8; j++) x += wsum[j];
        wsuf[t] = x;
    }
    if (t == 8) wsuf[8] = 0u;
    __syncthreads();
    unsigned suf_t = v + wsuf[wid + 1];
    bool found = (wsuf[0] >= PRE);
    if (found && suf_t >= PRE && (suf_t - s) < PRE) {
        unsigned acc = suf_t - s;
        int cut = 2048 + t * 8;
#pragma unroll
        for (int i = 7; i >= 0; i--) {
            if (acc + hv[i] >= PRE) { cut = 2048 + t * 8 + i; break; }
            acc += hv[i];
        }
        s_cut = cut;
    }
    __syncthreads();
    if (!found) {
        for (int i = t; i < 4096; i += 256) hist4[i] = 0u;
        __syncthreads();
        for (int id = t; id < NV; id += 256) {
            float4 vv = p[id];
            atomicAdd(&hist4[keyf(vv.x) >> 20], 1u);
            atomicAdd(&hist4[keyf(vv.y) >> 20], 1u);
            atomicAdd(&hist4[keyf(vv.z) >> 20], 1u);
            atomicAdd(&hist4[keyf(vv.w) >> 20], 1u);
        }
        __syncthreads();
        if (t == 0) {
            unsigned acc = 0;
            int cut = 0;
            for (int c = 4095; c >= 0; c--) {
                unsigned h = hist4[c];
                if (acc + h >= PRE) { cut = c; break; }
                acc += h;
            }
            s_cut = cut;
        }
        __syncthreads();
    }
    int cut = s_cut;
    if (t == 0 && blockIdx.x == 0) g_cut[b] = cut;
    if (t == 0) s_cnt = 0u;
    __syncthreads();
    int base = blockIdx.x * 2048;
    if (base + 2048 <= NV) {
        float4 vv[8];
#pragma unroll
        for (int k = 0; k < 8; k++) vv[k] = p[base + t + 256 * k];
#pragma unroll
        for (int k = 0; k < 8; k++) {
            int id = base + t + 256 * k;
            unsigned kk[4] = {keyf(vv[k].x), keyf(vv[k].y), keyf(vv[k].z), keyf(vv[k].w)};
#pragma unroll
            for (int q = 0; q < 4; q++) {
                if ((int)(kk[q] >> 20) >= cut) {
                    unsigned r = atomicAdd(&s_cnt, 1u);
                    if (r < STAGE)
                        stage[r] = ((ull)kk[q] << 32) | (unsigned)(~(4 * id + q));
                }
            }
        }
    } else {
        for (int k = 0; k < 8; k++) {
            int id = base + t + 256 * k;
            if (id < NV) {
                float4 vv = p[id];
                unsigned kk[4] = {keyf(vv.x), keyf(vv.y), keyf(vv.z), keyf(vv.w)};
#pragma unroll
                for (int q = 0; q < 4; q++) {
                    if ((int)(kk[q] >> 20) >= cut) {
                        unsigned r = atomicAdd(&s_cnt, 1u);
                        if (r < STAGE)
                            stage[r] = ((ull)kk[q] << 32) | (unsigned)(~(4 * id + q));
                    }
                }
            }
        }
    }
    __syncthreads();
    if (t == 0) {
        unsigned c = s_cnt < STAGE ? s_cnt : STAGE;
        s_base = atomicAdd(&g_ccount[b], c);
    }
    __syncthreads();
    unsigned c = s_cnt < STAGE ? s_cnt : STAGE;
    for (unsigned r = t; r < c; r += 256) {
        unsigned pos = s_base + r;
        if (pos < CANDMAX) g_cand[b][pos] = stage[r];
    }
}

#define CSW(a, c, d) { if ((d) ? ((a) < (c)) : ((a) > (c))) { ull _t = (a); (a) = (c); (c) = _t; } }
#define KM(e, o) ((kmax) ? ((e) > (o) ? (e) : (o)) : ((e) < (o) ? (e) : (o)))
#define SHFLP() { \
    int m = j >> 2; \
    bool kmax = (desc != ((tid & m) != 0)); \
    ull o0 = __shfl_xor_sync(0xffffffffu, e0, m); \
    ull o1 = __shfl_xor_sync(0xffffffffu, e1, m); \
    ull o2 = __shfl_xor_sync(0xffffffffu, e2, m); \
    ull o3 = __shfl_xor_sync(0xffffffffu, e3, m); \
    e0 = KM(e0, o0); e1 = KM(e1, o1); e2 = KM(e2, o2); e3 = KM(e3, o3); }

__global__ void __launch_bounds__(1024)
k_sortdecode(const float* __restrict__ reg, const float* __restrict__ anchors) {
    __shared__ ull sk[CANDMAX];
    __shared__ int swsum[32];
    __shared__ unsigned fh[256];
    __shared__ int s_fcut, s_kept;
    int b = blockIdx.x;
    int tid = threadIdx.x;
    int lane = tid & 31, wid = tid >> 5;
    unsigned n = g_ccount[b];
    if (n > CANDMAX) n = CANDMAX;
    int cut = g_cut[b];
    int b4 = 4 * tid;
    ull c0 = (b4 + 0 < (int)n) ? g_cand[b][b4 + 0] : 0ULL;
    ull c1 = (b4 + 1 < (int)n) ? g_cand[b][b4 + 1] : 0ULL;
    ull c2 = (b4 + 2 < (int)n) ? g_cand[b][b4 + 2] : 0ULL;
    ull c3 = (b4 + 3 < (int)n) ? g_cand[b][b4 + 3] : 0ULL;
    if (tid < 256) fh[tid] = 0u;
    __syncthreads();
#define FH(ci, off) { if (b4 + off < (int)n) { unsigned key = (unsigned)((ci) >> 32); \
        if ((int)(key >> 20) == cut) atomicAdd(&fh[(key >> 12) & 0xFF], 1u); } }
    FH(c0, 0) FH(c1, 1) FH(c2, 2) FH(c3, 3)
#undef FH
    __syncthreads();
    if (tid == 0) {
        unsigned tie = 0;
        for (int f = 0; f < 256; f++) tie += fh[f];
        int nab = (int)n - (int)tie;
        int acc = 0, fcut = 0, kept = (int)n;
        for (int f = 255; f >= 0; f--) {
            if (nab + acc + (int)fh[f] >= PRE) { fcut = f; kept = nab + acc + (int)fh[f]; break; }
            acc += (int)fh[f];
        }
        s_fcut = fcut;
        s_kept = kept;
    }
    __syncthreads();
    int kept = s_kept, fcut = s_fcut;
    ull e0 = 0, e1 = 0, e2 = 0, e3 = 0;
    if (kept <= 2048) {
        int p0 = 0, p1 = 0, p2 = 0, p3 = 0;
#define PRED(ci, pi, off) { if (b4 + off < (int)n) { unsigned key = (unsigned)((ci) >> 32); \
        pi = ((int)(key >> 20) > cut) || ((int)((key >> 12) & 0xFF) >= fcut); } }
        PRED(c0, p0, 0) PRED(c1, p1, 1) PRED(c2, p2, 2) PRED(c3, p3, 3)
#undef PRED
        int cnt = p0 + p1 + p2 + p3;
        int v = cnt;
        for (int o = 1; o < 32; o <<= 1) {
            int t2 = __shfl_up_sync(0xffffffffu, v, o);
            if (lane >= o) v += t2;
        }
        if (lane == 31) swsum[wid] = v;
        __syncthreads();
        if (wid == 0) {
            int x = swsum[lane];
            for (int o = 1; o < 32; o <<= 1) {
                int t2 = __shfl_up_sync(0xffffffffu, x, o);
                if (lane >= o) x += t2;
            }
            swsum[lane] = x;
        }
        __syncthreads();
        int excl = v - cnt + (wid ? swsum[wid - 1] : 0);
        sk[tid] = 0ULL;
        sk[tid + 1024] = 0ULL;
        __syncthreads();
        int pos = excl;
        if (p0) sk[pos++] = c0;
        if (p1) sk[pos++] = c1;
        if (p2) sk[pos++] = c2;
        if (p3) sk[pos++] = c3;
        __syncthreads();
        bool act = (tid < 512);
        if (act) {
            e0 = sk[b4]; e1 = sk[b4 + 1]; e2 = sk[b4 + 2]; e3 = sk[b4 + 3];
            CSW(e0, e1, true);
            CSW(e2, e3, false);
        }
        for (int k = 4; k <= 2048; k <<= 1) {
            bool desc = ((b4 & k) == 0);
            for (int j = k >> 1; j >= 128; j >>= 1) {
                if (act) { sk[b4] = e0; sk[b4 + 1] = e1; sk[b4 + 2] = e2; sk[b4 + 3] = e3; }
                __syncthreads();
                if (act) {
                    int m = j >> 2;
                    int pt = 4 * (tid ^ m);
                    bool kmax = (desc != ((tid & m) != 0));
                    ull o0 = sk[pt], o1 = sk[pt + 1], o2 = sk[pt + 2], o3 = sk[pt + 3];
                    e0 = KM(e0, o0); e1 = KM(e1, o1); e2 = KM(e2, o2); e3 = KM(e3, o3);
                }
                __syncthreads();
            }
            if (act) {
                int jstart = (k >> 1) < 64 ? (k >> 1) : 64;
                for (int j = jstart; j >= 4; j >>= 1) SHFLP()
                CSW(e0, e2, desc); CSW(e1, e3, desc);
                CSW(e0, e1, desc); CSW(e2, e3, desc);
            }
        }
        if (act) { sk[b4] = e0; sk[b4 + 1] = e1; sk[b4 + 2] = e2; sk[b4 + 3] = e3; }
        __syncthreads();
    } else {
        e0 = c0; e1 = c1; e2 = c2; e3 = c3;
        CSW(e0, e1, true);
        CSW(e2, e3, false);
        for (int k = 4; k <= CANDMAX; k <<= 1) {
            bool desc = ((b4 & k) == 0);
            for (int j = k >> 1; j >= 128; j >>= 1) {
                sk[b4] = e0; sk[b4 + 1] = e1; sk[b4 + 2] = e2; sk[b4 + 3] = e3;
                __syncthreads();
                int m = j >> 2;
                int pt = 4 * (tid ^ m);
                bool kmax = (desc != ((tid & m) != 0));
                ull o0 = sk[pt], o1 = sk[pt + 1], o2 = sk[pt + 2], o3 = sk[pt + 3];
                e0 = KM(e0, o0); e1 = KM(e1, o1); e2 = KM(e2, o2); e3 = KM(e3, o3);
                __syncthreads();
            }
            int jstart = (k >> 1) < 64 ? (k >> 1) : 64;
            for (int j = jstart; j >= 4; j >>= 1) SHFLP()
            CSW(e0, e2, desc); CSW(e1, e3, desc);
            CSW(e0, e1, desc); CSW(e2, e3, desc);
        }
        sk[b4] = e0; sk[b4 + 1] = e1; sk[b4 + 2] = e2; sk[b4 + 3] = e3;
        __syncthreads();
    }
    float4 box[2];
    int val[2];
#pragma unroll
    for (int q = 0; q < 2; q++) {
        int e = 2 * tid + q;
        val[q] = 0;
        box[q] = make_float4(0.f, 0.f, 0.f, 0.f);
        if (e < PRE) {
            unsigned idx = ~(unsigned)(sk[e] & 0xFFFFFFFFULL);
            const float* a = anchors + ((size_t)b * NN + idx) * 4;
            const float* r = reg + ((size_t)b * NN + idx) * 4;
            float a0 = a[0], a1 = a[1], a2 = a[2], a3 = a[3];
            float dx = r[0], dy = r[1], dw = r[2], dh = r[3];
            float aw = a2 - a0, ah = a3 - a1;
            float acx = a0 + 0.5f * aw, acy = a1 + 0.5f * ah;
            float pcx = dx * aw + acx, pcy = dy * ah + acy;
            float pw = expf(dw) * aw, ph = expf(dh) * ah;
            float x1 = pcx - 0.5f * pw, y1 = pcy - 0.5f * ph;
            float x2 = pcx + 0.5f * pw, y2 = pcy + 0.5f * ph;
            x1 = fminf(fmaxf(x1, 0.f), 1333.f);
            y1 = fminf(fmaxf(y1, 0.f), 800.f);
            x2 = fminf(fmaxf(x2, 0.f), 1333.f);
            y2 = fminf(fmaxf(y2, 0.f), 800.f);
            float w = x2 - x1, h = y2 - y1;
            val[q] = (w >= 0.001f && h >= 0.001f) ? 1 : 0;
            box[q] = make_float4(x1, y1, x2, y2);
        }
    }
    int pairsum = val[0] + val[1];
    int v = pairsum;
    for (int o = 1; o < 32; o <<= 1) {
        int t2 = __shfl_up_sync(0xffffffffu, v, o);
        if (lane >= o) v += t2;
    }
    if (lane == 31) swsum[wid] = v;
    __syncthreads();
    if (wid == 0) {
        int x = swsum[lane];
        for (int o = 1; o < 32; o <<= 1) {
            int t2 = __shfl_up_sync(0xffffffffu, x, o);
            if (lane >= o) x += t2;
        }
        swsum[lane] = x;
    }
    __syncthreads();
    int incl = v + (wid ? swsum[wid - 1] : 0);
    int excl = incl - pairsum;
    int nv = swsum[31];
    int ea = 2 * tid, eb = 2 * tid + 1;
    int rank0 = excl;
    int rank1 = excl + val[0];
    int pos0 = val[0] ? rank0 : nv + (ea - rank0);
    int pos1 = val[1] ? rank1 : nv + (eb - rank1);
    if (ea < PRE) {
        g_boxes[b][pos0] = box[0];
        g_area[b][pos0] = (box[0].z - box[0].x) * (box[0].w - box[0].y);
    }
    if (eb < PRE) {
        g_boxes[b][pos1] = box[1];
        g_area[b][pos1] = (box[1].z - box[1].x) * (box[1].w - box[1].y);
    }
    if (tid == 0) g_nvalid[b] = nv;
}

#define C_HI 0.41177000588f   /* (7/17)*(1+1e-5) */
#define C_LO 0.41176177060f   /* (7/17)*(1-1e-5) */

// 256-thread blocks: one row-block x 4 column-tiles (groups g=0..3).
// Thresholds via FFMA from carea (4B LDS) instead of staged float2 (8B LDS).
__global__ void __launch_bounds__(256) k_mask() {
    int b = blockIdx.y;
    int g = threadIdx.x >> 6;
    int t = threadIdx.x & 63;
    int lin = blockIdx.x, rblk = 0;
    for (;;) {
        int cnt = (32 - rblk + 3) >> 2;
        if (lin < cnt) break;
        lin -= cnt;
        rblk++;
    }
    int cblk = rblk + 4 * lin + g;
    bool validc = (cblk < 32);
    __shared__ float4 cbox[4][64];
    __shared__ float carea[4][64];
    if (validc) {
        int j0 = (cblk << 6) + t;
        cbox[g][t] = (j0 < PRE) ? g_boxes[b][j0] : make_float4(-1.f, -1.f, -1.f, -1.f);
        carea[g][t] = (j0 < PRE) ? g_area[b][j0] : 0.f;
    }
    __syncthreads();
    if (!validc) return;
    int i = (rblk << 6) + t;   // < PRE always (max 1983+... row blocks 0..31 -> max 2047? no: rblk<=31, i<=2047)
    if (i >= PRE) return;
    float4 bi = g_boxes[b][i];
    float areai = g_area[b][i];
    float kAhi = C_HI * areai;
    float kAlo = C_LO * areai;
    unsigned blo = 0u, bhi = 0u, alo = 0u, ahi = 0u;
#define IOUB(c, BL, AL, SH) { \
        float4 bj = cbox[g][c]; \
        float aj = carea[g][c]; \
        float w = fmaxf(fminf(bi.z, bj.z) - fmaxf(bi.x, bj.x), 0.f); \
        float h = fminf(bi.w, bj.w) - fmaxf(bi.y, bj.y); \
        float inter = w * h; \
        bool s1 = inter > fmaf(C_HI, aj, kAhi); \
        bool a1 = (!s1) && (inter >= fmaf(C_LO, aj, kAlo)); \
        BL |= ((unsigned)s1) << (SH); \
        AL |= ((unsigned)a1) << (SH); }
    if (cblk == rblk) {
        for (int c = t + 1; c < 64; c++) {
            if (c < 32) { IOUB(c, blo, alo, c) }
            else { IOUB(c, bhi, ahi, c - 32) }
        }
    } else {
#pragma unroll
        for (int c = 0; c < 32; c++) { IOUB(c, blo, alo, c) }
#pragma unroll
        for (int c = 32; c < 64; c++) { IOUB(c, bhi, ahi, c - 32) }
    }
#undef IOUB
    ull bits = ((ull)bhi << 32) | blo;
    ull amb = ((ull)ahi << 32) | alo;
    while (amb) {  // rare: exact reference-formula decision
        int c = __ffsll(amb) - 1;
        amb &= amb - 1;
        float4 bj = cbox[g][c];
        float w = fmaxf(fminf(bi.z, bj.z) - fmaxf(bi.x, bj.x), 0.f);
        float h = fmaxf(fminf(bi.w, bj.w) - fmaxf(bi.y, bj.y), 0.f);
        float inter = w * h;
        float um = fmaxf((areai + carea[g][c]) - inter, 1e-8f);
        if (__fdiv_rn(inter, um) > 0.7f) bits |= 1ULL << c;
    }
    g_mask[b][i][cblk] = bits;
}

__global__ void __launch_bounds__(256) k_scan(float4* __restrict__ out) {
    __shared__ ull ring[4][16][32];
    __shared__ int sel[POST];
    __shared__ int skc;
    int b = blockIdx.x;
    int tid = threadIdx.x;
    if (tid < 32) {
        int lane = tid;
        int nv = g_nvalid[b];
        int lo = lane * 64;
        ull rem;
        if (nv <= lo) rem = ~0ULL;
        else if (nv >= lo + 64) rem = 0ULL;
        else rem = (~0ULL) << (nv - lo);
        for (int nb = 0; nb < 3; nb++) {
#pragma unroll
            for (int q = 0; q < 16; q++)
                CP8(smaddr(&ring[nb][q][lane]), &g_mask[b][nb * 16 + q][lane]);
            CPCOMMIT();
        }
        int limit = (PRE < nv) ? PRE : nv;
        int kc = 0, w = 0;
        ull r = 0ULL;
        for (int bt = 0; bt < PRE / 16; bt++) {
            CPWAIT2();
            __syncwarp();
            int base = bt * 16;
            if (base >= limit) break;
            if ((base & 63) == 0) {
                w = base >> 6;
                r = __shfl_sync(0xffffffffu, rem, w);
            }
            ull m[16];
            unsigned keptm = 0;
            if (lane == 0) {
#pragma unroll
                for (int q = 0; q < 16; q++) m[q] = ring[bt & 3][q][w];
                int off = base & 63;
#pragma unroll
                for (int q = 0; q < 16; q++) {
                    int row = base + q;
                    bool keep = (row < limit) && !((r >> (off + q)) & 1ULL);
                    if (keep) {
                        if (kc < POST) sel[kc] = row;
                        kc++;
                        keptm |= 1u << q;
                        r |= m[q];
                    }
                }
            }
            keptm = __shfl_sync(0xffffffffu, keptm, 0);
            ull acc = 0ULL;
#pragma unroll
            for (int q = 0; q < 16; q++)
                if ((keptm >> q) & 1u) acc |= ring[bt & 3][q][lane];
            if (lane >= w) rem |= acc;
            kc = __shfl_sync(0xffffffffu, kc, 0);
            if (kc >= POST) break;
            int nb = bt + 3;
            if (nb < PRE / 16) {
#pragma unroll
                for (int q = 0; q < 16; q++)
                    CP8(smaddr(&ring[nb & 3][q][lane]), &g_mask[b][nb * 16 + q][lane]);
            }
            CPCOMMIT();
        }
        CPWAITALL();
        if (lane == 0) skc = (kc < POST) ? kc : POST;
    }
    __syncthreads();
    int kc = skc;
    for (int k = tid; k < POST; k += blockDim.x) {
        float4 v = make_float4(0.f, 0.f, 0.f, 0.f);
        if (k < kc) v = g_boxes[b][sel[k]];
        out[(size_t)b * POST + k] = v;
    }
    // restore state for next graph replay
    for (int k = tid; k < 2048; k += blockDim.x) g_hist[b][k] = 0u;
    if (tid == 0) g_ccount[b] = 0u;
}

extern "C" void kernel_launch(void* const* d_in, const int* in_sizes, int n_in,
                              void* d_out, int out_size) {
    const float* cls = (const float*)d_in[0];
    const float* reg = (const float*)d_in[1];
    const float* anchors = (const float*)d_in[2];
    float4* out = (float4*)d_out;

    k_hist<<<dim3(NBLK, BB), 256>>>(cls);
    k_compact<<<dim3(NBLK, BB), 256>>>(cls);
    k_sortdecode<<<BB, 1024>>>(reg, anchors);
    k_mask<<<dim3(144, BB), 256>>>();
    k_scan<<<BB, 256>>>(out);
}

// round 14
// speedup vs baseline: 1.0146x; 1.0146x over previous
#include <cuda_runtime.h>
#include <math.h>

#define BB 16
#define NN 300000
#define NV 75000
#define NBLK 37
#define PRE 2000
#define POST 1000
#define CANDMAX 4096
#define MASKW 32
#define STAGE 1024

typedef unsigned long long ull;

__device__ unsigned g_hist[BB][2048];   // zeroed by k_scan for next replay
__device__ int g_cut[BB];
__device__ unsigned g_ccount[BB];       // zeroed by k_scan for next replay
__device__ ull g_cand[BB][CANDMAX];
__device__ float4 g_boxes[BB][PRE];
__device__ float g_area[BB][PRE];
__device__ int g_nvalid[BB];
__device__ ull g_mask[BB][PRE][MASKW];

__device__ __forceinline__ unsigned keyf(float f) {
    unsigned u = __float_as_uint(f);
    return u ^ ((u >> 31) ? 0xFFFFFFFFu : 0x80000000u);
}

__device__ __forceinline__ unsigned smaddr(const void* p) {
    return (unsigned)__cvta_generic_to_shared(p);
}
#define CP8(dst, src) asm volatile("cp.async.ca.shared.global [%0], [%1], 8;" :: "r"(dst), "l"(src))
#define CPCOMMIT() asm volatile("cp.async.commit_group;")
#define CPWAIT2() asm volatile("cp.async.wait_group 2;")
#define CPWAITALL() asm volatile("cp.async.wait_all;")

__global__ void __launch_bounds__(256) k_hist(const float* __restrict__ cls) {
    __shared__ unsigned sh[2048];
    int b = blockIdx.y;
    int t = threadIdx.x;
    for (int i = t; i < 2048; i += 256) sh[i] = 0u;
    __syncthreads();
    const float4* __restrict__ p = (const float4*)(cls + (size_t)b * NN);
    int base = blockIdx.x * 2048;
    if (base + 2048 <= NV) {
        float4 v[8];
#pragma unroll
        for (int k = 0; k < 8; k++) v[k] = p[base + t + 256 * k];
#pragma unroll
        for (int k = 0; k < 8; k++) {
            unsigned kk[4] = {keyf(v[k].x), keyf(v[k].y), keyf(v[k].z), keyf(v[k].w)};
#pragma unroll
            for (int q = 0; q < 4; q++)
                if (kk[q] >= 0x80000000u) atomicAdd(&sh[(kk[q] >> 20) - 2048], 1u);
        }
    } else {
        for (int k = 0; k < 8; k++) {
            int id = base + t + 256 * k;
            if (id < NV) {
                float4 v = p[id];
                unsigned kk[4] = {keyf(v.x), keyf(v.y), keyf(v.z), keyf(v.w)};
#pragma unroll
                for (int q = 0; q < 4; q++)
                    if (kk[q] >= 0x80000000u) atomicAdd(&sh[(kk[q] >> 20) - 2048], 1u);
            }
        }
    }
    __syncthreads();
    for (int i = t; i < 2048; i += 256) {
        unsigned c = sh[i];
        if (c) atomicAdd(&g_hist[b][i], c);
    }
}

__global__ void __launch_bounds__(256) k_compact(const float* __restrict__ cls) {
    __shared__ ull stage[STAGE];
    __shared__ unsigned hist4[4096];   // cold path only
    __shared__ unsigned wsum[8];
    __shared__ unsigned wsuf[9];
    __shared__ int s_cut;
    __shared__ unsigned s_cnt, s_base;
    int b = blockIdx.y;
    int t = threadIdx.x;
    int lane = t & 31, wid = t >> 5;
    const float4* __restrict__ p = (const float4*)(cls + (size_t)b * NN);
    unsigned hv[8];
    unsigned s = 0;
#pragma unroll
    for (int q = 0; q < 8; q++) { hv[q] = g_hist[b][t * 8 + q]; s += hv[q]; }
    unsigned v = s;
#pragma unroll
    for (int o = 1; o < 32; o <<= 1) {
        unsigned t2 = __shfl_down_sync(0xffffffffu, v, o);
        if (lane + o < 32) v += t2;
    }
    if (lane == 0) wsum[wid] = v;
    __syncthreads();
    if (t < 8) {
        unsigned x = 0;
        for (int j = t; j < 8; j++) x += wsum[j];
        wsuf[t] = x;
    }
    if (t == 8) wsuf[8] = 0u;
    __syncthreads();
    unsigned suf_t = v + wsuf[wid + 1];
    bool found = (wsuf[0] >= PRE);
    if (found && suf_t >= PRE && (suf_t - s) < PRE) {
        unsigned acc = suf_t - s;
        int cut = 2048 + t * 8;
#pragma unroll
        for (int i = 7; i >= 0; i--) {
            if (acc + hv[i] >= PRE) { cut = 2048 + t * 8 + i; break; }
            acc += hv[i];
        }
        s_cut = cut;
    }
    __syncthreads();
    if (!found) {
        for (int i = t; i < 4096; i += 256) hist4[i] = 0u;
        __syncthreads();
        for (int id = t; id < NV; id += 256) {
            float4 vv = p[id];
            atomicAdd(&hist4[keyf(vv.x) >> 20], 1u);
            atomicAdd(&hist4[keyf(vv.y) >> 20], 1u);
            atomicAdd(&hist4[keyf(vv.z) >> 20], 1u);
            atomicAdd(&hist4[keyf(vv.w) >> 20], 1u);
        }
        __syncthreads();
        if (t == 0) {
            unsigned acc = 0;
            int cut = 0;
            for (int c = 4095; c >= 0; c--) {
                unsigned h = hist4[c];
                if (acc + h >= PRE) { cut = c; break; }
                acc += h;
            }
            s_cut = cut;
        }
        __syncthreads();
    }
    int cut = s_cut;
    if (t == 0 && blockIdx.x == 0) g_cut[b] = cut;
    if (t == 0) s_cnt = 0u;
    __syncthreads();
    int base = blockIdx.x * 2048;
    if (base + 2048 <= NV) {
        float4 vv[8];
#pragma unroll
        for (int k = 0; k < 8; k++) vv[k] = p[base + t + 256 * k];
#pragma unroll
        for (int k = 0; k < 8; k++) {
            int id = base + t + 256 * k;
            unsigned kk[4] = {keyf(vv[k].x), keyf(vv[k].y), keyf(vv[k].z), keyf(vv[k].w)};
#pragma unroll
            for (int q = 0; q < 4; q++) {
                if ((int)(kk[q] >> 20) >= cut) {
                    unsigned r = atomicAdd(&s_cnt, 1u);
                    if (r < STAGE)
                        stage[r] = ((ull)kk[q] << 32) | (unsigned)(~(4 * id + q));
                }
            }
        }
    } else {
        for (int k = 0; k < 8; k++) {
            int id = base + t + 256 * k;
            if (id < NV) {
                float4 vv = p[id];
                unsigned kk[4] = {keyf(vv.x), keyf(vv.y), keyf(vv.z), keyf(vv.w)};
#pragma unroll
                for (int q = 0; q < 4; q++) {
                    if ((int)(kk[q] >> 20) >= cut) {
                        unsigned r = atomicAdd(&s_cnt, 1u);
                        if (r < STAGE)
                            stage[r] = ((ull)kk[q] << 32) | (unsigned)(~(4 * id + q));
                    }
                }
            }
        }
    }
    __syncthreads();
    if (t == 0) {
        unsigned c = s_cnt < STAGE ? s_cnt : STAGE;
        s_base = atomicAdd(&g_ccount[b], c);
    }
    __syncthreads();
    unsigned c = s_cnt < STAGE ? s_cnt : STAGE;
    for (unsigned r = t; r < c; r += 256) {
        unsigned pos = s_base + r;
        if (pos < CANDMAX) g_cand[b][pos] = stage[r];
    }
}

#define CSW(a, c, d) { if ((d) ? ((a) < (c)) : ((a) > (c))) { ull _t = (a); (a) = (c); (c) = _t; } }
#define KM(e, o) ((kmax) ? ((e) > (o) ? (e) : (o)) : ((e) < (o) ? (e) : (o)))
#define SHFLP() { \
    int m = j >> 2; \
    bool kmax = (desc != ((tid & m) != 0)); \
    ull o0 = __shfl_xor_sync(0xffffffffu, e0, m); \
    ull o1 = __shfl_xor_sync(0xffffffffu, e1, m); \
    ull o2 = __shfl_xor_sync(0xffffffffu, e2, m); \
    ull o3 = __shfl_xor_sync(0xffffffffu, e3, m); \
    e0 = KM(e0, o0); e1 = KM(e1, o1); e2 = KM(e2, o2); e3 = KM(e3, o3); }

__global__ void __launch_bounds__(1024)
k_sortdecode(const float* __restrict__ reg, const float* __restrict__ anchors) {
    __shared__ ull sk[CANDMAX];
    __shared__ int swsum[32];
    __shared__ unsigned fh[256];
    __shared__ unsigned fw[8];
    __shared__ unsigned fwsuf[9];
    __shared__ int s_fcut, s_kept;
    int b = blockIdx.x;
    int tid = threadIdx.x;
    int lane = tid & 31, wid = tid >> 5;
    unsigned n = g_ccount[b];
    if (n > CANDMAX) n = CANDMAX;
    int cut = g_cut[b];
    int b4 = 4 * tid;
    ull c0 = (b4 + 0 < (int)n) ? g_cand[b][b4 + 0] : 0ULL;
    ull c1 = (b4 + 1 < (int)n) ? g_cand[b][b4 + 1] : 0ULL;
    ull c2 = (b4 + 2 < (int)n) ? g_cand[b][b4 + 2] : 0ULL;
    ull c3 = (b4 + 3 < (int)n) ? g_cand[b][b4 + 3] : 0ULL;
    if (tid < 256) fh[tid] = 0u;
    if (tid == 0) { s_fcut = 0; s_kept = (int)n; }
    __syncthreads();
#define FH(ci, off) { if (b4 + off < (int)n) { unsigned key = (unsigned)((ci) >> 32); \
        if ((int)(key >> 20) == cut) atomicAdd(&fh[(key >> 12) & 0xFF], 1u); } }
    FH(c0, 0) FH(c1, 1) FH(c2, 2) FH(c3, 3)
#undef FH
    __syncthreads();
    // ---- parallel fine-cut: 256-thread suffix scan over fh ----
    unsigned fhv = 0, fincl = 0;
    if (tid < 256) {
        fhv = fh[tid];
        unsigned v2 = fhv;
#pragma unroll
        for (int o = 1; o < 32; o <<= 1) {
            unsigned t2 = __shfl_down_sync(0xffffffffu, v2, o);
            if (lane + o < 32) v2 += t2;
        }
        if (lane == 0) fw[wid] = v2;
        fincl = v2;
    }
    __syncthreads();
    if (tid < 8) {
        unsigned x = 0;
        for (int j = tid; j < 8; j++) x += fw[j];
        fwsuf[tid] = x;
    }
    if (tid == 8) fwsuf[8] = 0u;
    __syncthreads();
    if (tid < 256) {
        unsigned incl = fincl + fwsuf[wid + 1];  // inclusive suffix sum at bin tid
        int nab = (int)n - (int)fwsuf[0];        // candidates strictly above cut bin
        if (nab + (int)incl >= PRE && nab + (int)(incl - fhv) < PRE) {
            s_fcut = tid;                        // unique crossing bin
            s_kept = nab + (int)incl;
        }
    }
    __syncthreads();
    int kept = s_kept, fcut = s_fcut;
    ull e0 = 0, e1 = 0, e2 = 0, e3 = 0;
    if (kept <= 2048) {
        int p0 = 0, p1 = 0, p2 = 0, p3 = 0;
#define PRED(ci, pi, off) { if (b4 + off < (int)n) { unsigned key = (unsigned)((ci) >> 32); \
        pi = ((int)(key >> 20) > cut) || ((int)((key >> 12) & 0xFF) >= fcut); } }
        PRED(c0, p0, 0) PRED(c1, p1, 1) PRED(c2, p2, 2) PRED(c3, p3, 3)
#undef PRED
        int cnt = p0 + p1 + p2 + p3;
        int v = cnt;
        for (int o = 1; o < 32; o <<= 1) {
            int t2 = __shfl_up_sync(0xffffffffu, v, o);
            if (lane >= o) v += t2;
        }
        if (lane == 31) swsum[wid] = v;
        __syncthreads();
        if (wid == 0) {
            int x = swsum[lane];
            for (int o = 1; o < 32; o <<= 1) {
                int t2 = __shfl_up_sync(0xffffffffu, x, o);
                if (lane >= o) x += t2;
            }
            swsum[lane] = x;
        }
        __syncthreads();
        int excl = v - cnt + (wid ? swsum[wid - 1] : 0);
        sk[tid] = 0ULL;
        sk[tid + 1024] = 0ULL;
        __syncthreads();
        int pos = excl;
        if (p0) sk[pos++] = c0;
        if (p1) sk[pos++] = c1;
        if (p2) sk[pos++] = c2;
        if (p3) sk[pos++] = c3;
        __syncthreads();
        bool act = (tid < 512);
        if (act) {
            e0 = sk[b4]; e1 = sk[b4 + 1]; e2 = sk[b4 + 2]; e3 = sk[b4 + 3];
            CSW(e0, e1, true);
            CSW(e2, e3, false);
        }
        for (int k = 4; k <= 2048; k <<= 1) {
            bool desc = ((b4 & k) == 0);
            for (int j = k >> 1; j >= 128; j >>= 1) {
                if (act) { sk[b4] = e0; sk[b4 + 1] = e1; sk[b4 + 2] = e2; sk[b4 + 3] = e3; }
                __syncthreads();
                if (act) {
                    int m = j >> 2;
                    int pt = 4 * (tid ^ m);
                    bool kmax = (desc != ((tid & m) != 0));
                    ull o0 = sk[pt], o1 = sk[pt + 1], o2 = sk[pt + 2], o3 = sk[pt + 3];
                    e0 = KM(e0, o0); e1 = KM(e1, o1); e2 = KM(e2, o2); e3 = KM(e3, o3);
                }
                __syncthreads();
            }
            if (act) {
                int jstart = (k >> 1) < 64 ? (k >> 1) : 64;
                for (int j = jstart; j >= 4; j >>= 1) SHFLP()
                CSW(e0, e2, desc); CSW(e1, e3, desc);
                CSW(e0, e1, desc); CSW(e2, e3, desc);
            }
        }
        if (act) { sk[b4] = e0; sk[b4 + 1] = e1; sk[b4 + 2] = e2; sk[b4 + 3] = e3; }
        __syncthreads();
    } else {
        e0 = c0; e1 = c1; e2 = c2; e3 = c3;
        CSW(e0, e1, true);
        CSW(e2, e3, false);
        for (int k = 4; k <= CANDMAX; k <<= 1) {
            bool desc = ((b4 & k) == 0);
            for (int j = k >> 1; j >= 128; j >>= 1) {
                sk[b4] = e0; sk[b4 + 1] = e1; sk[b4 + 2] = e2; sk[b4 + 3] = e3;
                __syncthreads();
                int m = j >> 2;
                int pt = 4 * (tid ^ m);
                bool kmax = (desc != ((tid & m) != 0));
                ull o0 = sk[pt], o1 = sk[pt + 1], o2 = sk[pt + 2], o3 = sk[pt + 3];
                e0 = KM(e0, o0); e1 = KM(e1, o1); e2 = KM(e2, o2); e3 = KM(e3, o3);
                __syncthreads();
            }
            int jstart = (k >> 1) < 64 ? (k >> 1) : 64;
            for (int j = jstart; j >= 4; j >>= 1) SHFLP()
            CSW(e0, e2, desc); CSW(e1, e3, desc);
            CSW(e0, e1, desc); CSW(e2, e3, desc);
        }
        sk[b4] = e0; sk[b4 + 1] = e1; sk[b4 + 2] = e2; sk[b4 + 3] = e3;
        __syncthreads();
    }
    float4 box[2];
    int val[2];
#pragma unroll
    for (int q = 0; q < 2; q++) {
        int e = 2 * tid + q;
        val[q] = 0;
        box[q] = make_float4(0.f, 0.f, 0.f, 0.f);
        if (e < PRE) {
            unsigned idx = ~(unsigned)(sk[e] & 0xFFFFFFFFULL);
            const float* a = anchors + ((size_t)b * NN + idx) * 4;
            const float* r = reg + ((size_t)b * NN + idx) * 4;
            float a0 = a[0], a1 = a[1], a2 = a[2], a3 = a[3];
            float dx = r[0], dy = r[1], dw = r[2], dh = r[3];
            float aw = a2 - a0, ah = a3 - a1;
            float acx = a0 + 0.5f * aw, acy = a1 + 0.5f * ah;
            float pcx = dx * aw + acx, pcy = dy * ah + acy;
            float pw = expf(dw) * aw, ph = expf(dh) * ah;
            float x1 = pcx - 0.5f * pw, y1 = pcy - 0.5f * ph;
            float x2 = pcx + 0.5f * pw, y2 = pcy + 0.5f * ph;
            x1 = fminf(fmaxf(x1, 0.f), 1333.f);
            y1 = fminf(fmaxf(y1, 0.f), 800.f);
            x2 = fminf(fmaxf(x2, 0.f), 1333.f);
            y2 = fminf(fmaxf(y2, 0.f), 800.f);
            float w = x2 - x1, h = y2 - y1;
            val[q] = (w >= 0.001f && h >= 0.001f) ? 1 : 0;
            box[q] = make_float4(x1, y1, x2, y2);
        }
    }
    int pairsum = val[0] + val[1];
    int v = pairsum;
    for (int o = 1; o < 32; o <<= 1) {
        int t2 = __shfl_up_sync(0xffffffffu, v, o);
        if (lane >= o) v += t2;
    }
    if (lane == 31) swsum[wid] = v;
    __syncthreads();
    if (wid == 0) {
        int x = swsum[lane];
        for (int o = 1; o < 32; o <<= 1) {
            int t2 = __shfl_up_sync(0xffffffffu, x, o);
            if (lane >= o) x += t2;
        }
        swsum[lane] = x;
    }
    __syncthreads();
    int incl = v + (wid ? swsum[wid - 1] : 0);
    int excl = incl - pairsum;
    int nv = swsum[31];
    int ea = 2 * tid, eb = 2 * tid + 1;
    int rank0 = excl;
    int rank1 = excl + val[0];
    int pos0 = val[0] ? rank0 : nv + (ea - rank0);
    int pos1 = val[1] ? rank1 : nv + (eb - rank1);
    if (ea < PRE) {
        g_boxes[b][pos0] = box[0];
        g_area[b][pos0] = (box[0].z - box[0].x) * (box[0].w - box[0].y);
    }
    if (eb < PRE) {
        g_boxes[b][pos1] = box[1];
        g_area[b][pos1] = (box[1].z - box[1].x) * (box[1].w - box[1].y);
    }
    if (tid == 0) g_nvalid[b] = nv;
}

#define C_HI 0.41177000588f   /* (7/17)*(1+1e-5) */
#define C_LO 0.41176177060f   /* (7/17)*(1-1e-5) */

// 256-thread blocks: one row-block x 4 column-tiles (groups g=0..3).
// Thresholds via FFMA from carea (4B LDS).
__global__ void __launch_bounds__(256) k_mask() {
    int b = blockIdx.y;
    int g = threadIdx.x >> 6;
    int t = threadIdx.x & 63;
    int lin = blockIdx.x, rblk = 0;
    for (;;) {
        int cnt = (32 - rblk + 3) >> 2;
        if (lin < cnt) break;
        lin -= cnt;
        rblk++;
    }
    int cblk = rblk + 4 * lin + g;
    bool validc = (cblk < 32);
    __shared__ float4 cbox[4][64];
    __shared__ float carea[4][64];
    if (validc) {
        int j0 = (cblk << 6) + t;
        cbox[g][t] = (j0 < PRE) ? g_boxes[b][j0] : make_float4(-1.f, -1.f, -1.f, -1.f);
        carea[g][t] = (j0 < PRE) ? g_area[b][j0] : 0.f;
    }
    __syncthreads();
    if (!validc) return;
    int i = (rblk << 6) + t;
    if (i >= PRE) return;
    float4 bi = g_boxes[b][i];
    float areai = g_area[b][i];
    float kAhi = C_HI * areai;
    float kAlo = C_LO * areai;
    unsigned blo = 0u, bhi = 0u, alo = 0u, ahi = 0u;
#define IOUB(c, BL, AL, SH) { \
        float4 bj = cbox[g][c]; \
        float aj = carea[g][c]; \
        float w = fmaxf(fminf(bi.z, bj.z) - fmaxf(bi.x, bj.x), 0.f); \
        float h = fminf(bi.w, bj.w) - fmaxf(bi.y, bj.y); \
        float inter = w * h; \
        bool s1 = inter > fmaf(C_HI, aj, kAhi); \
        bool a1 = (!s1) && (inter >= fmaf(C_LO, aj, kAlo)); \
        BL |= ((unsigned)s1) << (SH); \
        AL |= ((unsigned)a1) << (SH); }
    if (cblk == rblk) {
        for (int c = t + 1; c < 64; c++) {
            if (c < 32) { IOUB(c, blo, alo, c) }
            else { IOUB(c, bhi, ahi, c - 32) }
        }
    } else {
#pragma unroll
        for (int c = 0; c < 32; c++) { IOUB(c, blo, alo, c) }
#pragma unroll
        for (int c = 32; c < 64; c++) { IOUB(c, bhi, ahi, c - 32) }
    }
#undef IOUB
    ull bits = ((ull)bhi << 32) | blo;
    ull amb = ((ull)ahi << 32) | alo;
    while (amb) {  // rare: exact reference-formula decision
        int c = __ffsll(amb) - 1;
        amb &= amb - 1;
        float4 bj = cbox[g][c];
        float w = fmaxf(fminf(bi.z, bj.z) - fmaxf(bi.x, bj.x), 0.f);
        float h = fmaxf(fminf(bi.w, bj.w) - fmaxf(bi.y, bj.y), 0.f);
        float inter = w * h;
        float um = fmaxf((areai + carea[g][c]) - inter, 1e-8f);
        if (__fdiv_rn(inter, um) > 0.7f) bits |= 1ULL << c;
    }
    g_mask[b][i][cblk] = bits;
}

__global__ void __launch_bounds__(256) k_scan(float4* __restrict__ out) {
    __shared__ ull ring[4][16][32];
    __shared__ int sel[POST];
    __shared__ int skc;
    int b = blockIdx.x;
    int tid = threadIdx.x;
    if (tid < 32) {
        int lane = tid;
        int nv = g_nvalid[b];
        int lo = lane * 64;
        ull rem;
        if (nv <= lo) rem = ~0ULL;
        else if (nv >= lo + 64) rem = 0ULL;
        else rem = (~0ULL) << (nv - lo);
        for (int nb = 0; nb < 3; nb++) {
#pragma unroll
            for (int q = 0; q < 16; q++)
                CP8(smaddr(&ring[nb][q][lane]), &g_mask[b][nb * 16 + q][lane]);
            CPCOMMIT();
        }
        int limit = (PRE < nv) ? PRE : nv;
        int kc = 0, w = 0;
        ull r = 0ULL;
        for (int bt = 0; bt < PRE / 16; bt++) {
            CPWAIT2();
            __syncwarp();
            int base = bt * 16;
            if (base >= limit) break;
            if ((base & 63) == 0) {
                w = base >> 6;
                r = __shfl_sync(0xffffffffu, rem, w);
            }
            ull m[16];
            unsigned keptm = 0;
            if (lane == 0) {
#pragma unroll
                for (int q = 0; q < 16; q++) m[q] = ring[bt & 3][q][w];
                int off = base & 63;
#pragma unroll
                for (int q = 0; q < 16; q++) {
                    int row = base + q;
                    bool keep = (row < limit) && !((r >> (off + q)) & 1ULL);
                    if (keep) {
                        if (kc < POST) sel[kc] = row;
                        kc++;
                        keptm |= 1u << q;
                        r |= m[q];
                    }
                }
            }
            keptm = __shfl_sync(0xffffffffu, keptm, 0);
            ull acc = 0ULL;
#pragma unroll
            for (int q = 0; q < 16; q++)
                if ((keptm >> q) & 1u) acc |= ring[bt & 3][q][lane];
            if (lane >= w) rem |= acc;
            kc = __shfl_sync(0xffffffffu, kc, 0);
            if (kc >= POST) break;
            int nb = bt + 3;
            if (nb < PRE / 16) {
#pragma unroll
                for (int q = 0; q < 16; q++)
                    CP8(smaddr(&ring[nb & 3][q][lane]), &g_mask[b][nb * 16 + q][lane]);
            }
            CPCOMMIT();
        }
        CPWAITALL();
        if (lane == 0) skc = (kc < POST) ? kc : POST;
    }
    __syncthreads();
    int kc = skc;
    for (int k = tid; k < POST; k += blockDim.x) {
        float4 v = make_float4(0.f, 0.f, 0.f, 0.f);
        if (k < kc) v = g_boxes[b][sel[k]];
        out[(size_t)b * POST + k] = v;
    }
    // restore state for next graph replay
    for (int k = tid; k < 2048; k += blockDim.x) g_hist[b][k] = 0u;
    if (tid == 0) g_ccount[b] = 0u;
}

extern "C" void kernel_launch(void* const* d_in, const int* in_sizes, int n_in,
                              void* d_out, int out_size) {
    const float* cls = (const float*)d_in[0];
    const float* reg = (const float*)d_in[1];
    const float* anchors = (const float*)d_in[2];
    float4* out = (float4*)d_out;

    k_hist<<<dim3(NBLK, BB), 256>>>(cls);
    k_compact<<<dim3(NBLK, BB), 256>>>(cls);
    k_sortdecode<<<BB, 1024>>>(reg, anchors);
    k_mask<<<dim3(144, BB), 256>>>();
    k_scan<<<BB, 256>>>(out);
}

// round 15
// speedup vs baseline: 1.0347x; 1.0198x over previous
#include <cuda_runtime.h>
#include <math.h>

#define BB 16
#define GRP 2
#define BPG (BB / GRP)
#define NN 300000
#define NV 75000
#define NBLK 37
#define PRE 2000
#define POST 1000
#define CANDMAX 4096
#define MASKW 32
#define STAGE 1024

typedef unsigned long long ull;

__device__ unsigned g_hist[BB][2048];   // zeroed by k_scan for next replay
__device__ int g_cut[BB];
__device__ unsigned g_ccount[BB];       // zeroed by k_scan for next replay
__device__ ull g_cand[BB][CANDMAX];
__device__ float4 g_boxes[BB][PRE];
__device__ float g_area[BB][PRE];
__device__ int g_nvalid[BB];
__device__ ull g_mask[BB][PRE][MASKW];

__device__ __forceinline__ unsigned keyf(float f) {
    unsigned u = __float_as_uint(f);
    return u ^ ((u >> 31) ? 0xFFFFFFFFu : 0x80000000u);
}

__device__ __forceinline__ unsigned smaddr(const void* p) {
    return (unsigned)__cvta_generic_to_shared(p);
}
#define CP8(dst, src) asm volatile("cp.async.ca.shared.global [%0], [%1], 8;" :: "r"(dst), "l"(src))
#define CPCOMMIT() asm volatile("cp.async.commit_group;")
#define CPWAIT2() asm volatile("cp.async.wait_group 2;")
#define CPWAITALL() asm volatile("cp.async.wait_all;")

__global__ void __launch_bounds__(256) k_hist(const float* __restrict__ cls, int b0) {
    __shared__ unsigned sh[2048];
    int b = blockIdx.y + b0;
    int t = threadIdx.x;
    for (int i = t; i < 2048; i += 256) sh[i] = 0u;
    __syncthreads();
    const float4* __restrict__ p = (const float4*)(cls + (size_t)b * NN);
    int base = blockIdx.x * 2048;
    if (base + 2048 <= NV) {
        float4 v[8];
#pragma unroll
        for (int k = 0; k < 8; k++) v[k] = p[base + t + 256 * k];
#pragma unroll
        for (int k = 0; k < 8; k++) {
            unsigned kk[4] = {keyf(v[k].x), keyf(v[k].y), keyf(v[k].z), keyf(v[k].w)};
#pragma unroll
            for (int q = 0; q < 4; q++)
                if (kk[q] >= 0x80000000u) atomicAdd(&sh[(kk[q] >> 20) - 2048], 1u);
        }
    } else {
        for (int k = 0; k < 8; k++) {
            int id = base + t + 256 * k;
            if (id < NV) {
                float4 v = p[id];
                unsigned kk[4] = {keyf(v.x), keyf(v.y), keyf(v.z), keyf(v.w)};
#pragma unroll
                for (int q = 0; q < 4; q++)
                    if (kk[q] >= 0x80000000u) atomicAdd(&sh[(kk[q] >> 20) - 2048], 1u);
            }
        }
    }
    __syncthreads();
    for (int i = t; i < 2048; i += 256) {
        unsigned c = sh[i];
        if (c) atomicAdd(&g_hist[b][i], c);
    }
}

__global__ void __launch_bounds__(256) k_compact(const float* __restrict__ cls, int b0) {
    __shared__ ull stage[STAGE];
    __shared__ unsigned hist4[4096];   // cold path only
    __shared__ unsigned wsum[8];
    __shared__ unsigned wsuf[9];
    __shared__ int s_cut;
    __shared__ unsigned s_cnt, s_base;
    int b = blockIdx.y + b0;
    int t = threadIdx.x;
    int lane = t & 31, wid = t >> 5;
    const float4* __restrict__ p = (const float4*)(cls + (size_t)b * NN);
    unsigned hv[8];
    unsigned s = 0;
#pragma unroll
    for (int q = 0; q < 8; q++) { hv[q] = g_hist[b][t * 8 + q]; s += hv[q]; }
    unsigned v = s;
#pragma unroll
    for (int o = 1; o < 32; o <<= 1) {
        unsigned t2 = __shfl_down_sync(0xffffffffu, v, o);
        if (lane + o < 32) v += t2;
    }
    if (lane == 0) wsum[wid] = v;
    __syncthreads();
    if (t < 8) {
        unsigned x = 0;
        for (int j = t; j < 8; j++) x += wsum[j];
        wsuf[t] = x;
    }
    if (t == 8) wsuf[8] = 0u;
    __syncthreads();
    unsigned suf_t = v + wsuf[wid + 1];
    bool found = (wsuf[0] >= PRE);
    if (found && suf_t >= PRE && (suf_t - s) < PRE) {
        unsigned acc = suf_t - s;
        int cut = 2048 + t * 8;
#pragma unroll
        for (int i = 7; i >= 0; i--) {
            if (acc + hv[i] >= PRE) { cut = 2048 + t * 8 + i; break; }
            acc += hv[i];
        }
        s_cut = cut;
    }
    __syncthreads();
    if (!found) {
        for (int i = t; i < 4096; i += 256) hist4[i] = 0u;
        __syncthreads();
        for (int id = t; id < NV; id += 256) {
            float4 vv = p[id];
            atomicAdd(&hist4[keyf(vv.x) >> 20], 1u);
            atomicAdd(&hist4[keyf(vv.y) >> 20], 1u);
            atomicAdd(&hist4[keyf(vv.z) >> 20], 1u);
            atomicAdd(&hist4[keyf(vv.w) >> 20], 1u);
        }
        __syncthreads();
        if (t == 0) {
            unsigned acc = 0;
            int cut = 0;
            for (int c = 4095; c >= 0; c--) {
                unsigned h = hist4[c];
                if (acc + h >= PRE) { cut = c; break; }
                acc += h;
            }
            s_cut = cut;
        }
        __syncthreads();
    }
    int cut = s_cut;
    if (t == 0 && blockIdx.x == 0) g_cut[b] = cut;
    if (t == 0) s_cnt = 0u;
    __syncthreads();
    int base = blockIdx.x * 2048;
    if (base + 2048 <= NV) {
        float4 vv[8];
#pragma unroll
        for (int k = 0; k < 8; k++) vv[k] = p[base + t + 256 * k];
#pragma unroll
        for (int k = 0; k < 8; k++) {
            int id = base + t + 256 * k;
            unsigned kk[4] = {keyf(vv[k].x), keyf(vv[k].y), keyf(vv[k].z), keyf(vv[k].w)};
#pragma unroll
            for (int q = 0; q < 4; q++) {
                if ((int)(kk[q] >> 20) >= cut) {
                    unsigned r = atomicAdd(&s_cnt, 1u);
                    if (r < STAGE)
                        stage[r] = ((ull)kk[q] << 32) | (unsigned)(~(4 * id + q));
                }
            }
        }
    } else {
        for (int k = 0; k < 8; k++) {
            int id = base + t + 256 * k;
            if (id < NV) {
                float4 vv = p[id];
                unsigned kk[4] = {keyf(vv.x), keyf(vv.y), keyf(vv.z), keyf(vv.w)};
#pragma unroll
                for (int q = 0; q < 4; q++) {
                    if ((int)(kk[q] >> 20) >= cut) {
                        unsigned r = atomicAdd(&s_cnt, 1u);
                        if (r < STAGE)
                            stage[r] = ((ull)kk[q] << 32) | (unsigned)(~(4 * id + q));
                    }
                }
            }
        }
    }
    __syncthreads();
    if (t == 0) {
        unsigned c = s_cnt < STAGE ? s_cnt : STAGE;
        s_base = atomicAdd(&g_ccount[b], c);
    }
    __syncthreads();
    unsigned c = s_cnt < STAGE ? s_cnt : STAGE;
    for (unsigned r = t; r < c; r += 256) {
        unsigned pos = s_base + r;
        if (pos < CANDMAX) g_cand[b][pos] = stage[r];
    }
}

#define CSW(a, c, d) { if ((d) ? ((a) < (c)) : ((a) > (c))) { ull _t = (a); (a) = (c); (c) = _t; } }
#define KM(e, o) ((kmax) ? ((e) > (o) ? (e) : (o)) : ((e) < (o) ? (e) : (o)))
#define SHFLP() { \
    int m = j >> 2; \
    bool kmax = (desc != ((tid & m) != 0)); \
    ull o0 = __shfl_xor_sync(0xffffffffu, e0, m); \
    ull o1 = __shfl_xor_sync(0xffffffffu, e1, m); \
    ull o2 = __shfl_xor_sync(0xffffffffu, e2, m); \
    ull o3 = __shfl_xor_sync(0xffffffffu, e3, m); \
    e0 = KM(e0, o0); e1 = KM(e1, o1); e2 = KM(e2, o2); e3 = KM(e3, o3); }

__global__ void __launch_bounds__(1024)
k_sortdecode(const float* __restrict__ reg, const float* __restrict__ anchors, int b0) {
    __shared__ ull sk[CANDMAX];
    __shared__ int swsum[32];
    __shared__ unsigned fh[256];
    __shared__ unsigned fw[8];
    __shared__ unsigned fwsuf[9];
    __shared__ int s_fcut, s_kept;
    int b = blockIdx.x + b0;
    int tid = threadIdx.x;
    int lane = tid & 31, wid = tid >> 5;
    unsigned n = g_ccount[b];
    if (n > CANDMAX) n = CANDMAX;
    int cut = g_cut[b];
    int b4 = 4 * tid;
    ull c0 = (b4 + 0 < (int)n) ? g_cand[b][b4 + 0] : 0ULL;
    ull c1 = (b4 + 1 < (int)n) ? g_cand[b][b4 + 1] : 0ULL;
    ull c2 = (b4 + 2 < (int)n) ? g_cand[b][b4 + 2] : 0ULL;
    ull c3 = (b4 + 3 < (int)n) ? g_cand[b][b4 + 3] : 0ULL;
    if (tid < 256) fh[tid] = 0u;
    if (tid == 0) { s_fcut = 0; s_kept = (int)n; }
    __syncthreads();
#define FH(ci, off) { if (b4 + off < (int)n) { unsigned key = (unsigned)((ci) >> 32); \
        if ((int)(key >> 20) == cut) atomicAdd(&fh[(key >> 12) & 0xFF], 1u); } }
    FH(c0, 0) FH(c1, 1) FH(c2, 2) FH(c3, 3)
#undef FH
    __syncthreads();
    unsigned fhv = 0, fincl = 0;
    if (tid < 256) {
        fhv = fh[tid];
        unsigned v2 = fhv;
#pragma unroll
        for (int o = 1; o < 32; o <<= 1) {
            unsigned t2 = __shfl_down_sync(0xffffffffu, v2, o);
            if (lane + o < 32) v2 += t2;
        }
        if (lane == 0) fw[wid] = v2;
        fincl = v2;
    }
    __syncthreads();
    if (tid < 8) {
        unsigned x = 0;
        for (int j = tid; j < 8; j++) x += fw[j];
        fwsuf[tid] = x;
    }
    if (tid == 8) fwsuf[8] = 0u;
    __syncthreads();
    if (tid < 256) {
        unsigned incl = fincl + fwsuf[wid + 1];
        int nab = (int)n - (int)fwsuf[0];
        if (nab + (int)incl >= PRE && nab + (int)(incl - fhv) < PRE) {
            s_fcut = tid;
            s_kept = nab + (int)incl;
        }
    }
    __syncthreads();
    int kept = s_kept, fcut = s_fcut;
    ull e0 = 0, e1 = 0, e2 = 0, e3 = 0;
    if (kept <= 2048) {
        int p0 = 0, p1 = 0, p2 = 0, p3 = 0;
#define PRED(ci, pi, off) { if (b4 + off < (int)n) { unsigned key = (unsigned)((ci) >> 32); \
        pi = ((int)(key >> 20) > cut) || ((int)((key >> 12) & 0xFF) >= fcut); } }
        PRED(c0, p0, 0) PRED(c1, p1, 1) PRED(c2, p2, 2) PRED(c3, p3, 3)
#undef PRED
        int cnt = p0 + p1 + p2 + p3;
        int v = cnt;
        for (int o = 1; o < 32; o <<= 1) {
            int t2 = __shfl_up_sync(0xffffffffu, v, o);
            if (lane >= o) v += t2;
        }
        if (lane == 31) swsum[wid] = v;
        __syncthreads();
        if (wid == 0) {
            int x = swsum[lane];
            for (int o = 1; o < 32; o <<= 1) {
                int t2 = __shfl_up_sync(0xffffffffu, x, o);
                if (lane >= o) x += t2;
            }
            swsum[lane] = x;
        }
        __syncthreads();
        int excl = v - cnt + (wid ? swsum[wid - 1] : 0);
        sk[tid] = 0ULL;
        sk[tid + 1024] = 0ULL;
        __syncthreads();
        int pos = excl;
        if (p0) sk[pos++] = c0;
        if (p1) sk[pos++] = c1;
        if (p2) sk[pos++] = c2;
        if (p3) sk[pos++] = c3;
        __syncthreads();
        bool act = (tid < 512);
        if (act) {
            e0 = sk[b4]; e1 = sk[b4 + 1]; e2 = sk[b4 + 2]; e3 = sk[b4 + 3];
            CSW(e0, e1, true);
            CSW(e2, e3, false);
        }
        for (int k = 4; k <= 2048; k <<= 1) {
            bool desc = ((b4 & k) == 0);
            for (int j = k >> 1; j >= 128; j >>= 1) {
                if (act) { sk[b4] = e0; sk[b4 + 1] = e1; sk[b4 + 2] = e2; sk[b4 + 3] = e3; }
                __syncthreads();
                if (act) {
                    int m = j >> 2;
                    int pt = 4 * (tid ^ m);
                    bool kmax = (desc != ((tid & m) != 0));
                    ull o0 = sk[pt], o1 = sk[pt + 1], o2 = sk[pt + 2], o3 = sk[pt + 3];
                    e0 = KM(e0, o0); e1 = KM(e1, o1); e2 = KM(e2, o2); e3 = KM(e3, o3);
                }
                __syncthreads();
            }
            if (act) {
                int jstart = (k >> 1) < 64 ? (k >> 1) : 64;
                for (int j = jstart; j >= 4; j >>= 1) SHFLP()
                CSW(e0, e2, desc); CSW(e1, e3, desc);
                CSW(e0, e1, desc); CSW(e2, e3, desc);
            }
        }
        if (act) { sk[b4] = e0; sk[b4 + 1] = e1; sk[b4 + 2] = e2; sk[b4 + 3] = e3; }
        __syncthreads();
    } else {
        e0 = c0; e1 = c1; e2 = c2; e3 = c3;
        CSW(e0, e1, true);
        CSW(e2, e3, false);
        for (int k = 4; k <= CANDMAX; k <<= 1) {
            bool desc = ((b4 & k) == 0);
            for (int j = k >> 1; j >= 128; j >>= 1) {
                sk[b4] = e0; sk[b4 + 1] = e1; sk[b4 + 2] = e2; sk[b4 + 3] = e3;
                __syncthreads();
                int m = j >> 2;
                int pt = 4 * (tid ^ m);
                bool kmax = (desc != ((tid & m) != 0));
                ull o0 = sk[pt], o1 = sk[pt + 1], o2 = sk[pt + 2], o3 = sk[pt + 3];
                e0 = KM(e0, o0); e1 = KM(e1, o1); e2 = KM(e2, o2); e3 = KM(e3, o3);
                __syncthreads();
            }
            int jstart = (k >> 1) < 64 ? (k >> 1) : 64;
            for (int j = jstart; j >= 4; j >>= 1) SHFLP()
            CSW(e0, e2, desc); CSW(e1, e3, desc);
            CSW(e0, e1, desc); CSW(e2, e3, desc);
        }
        sk[b4] = e0; sk[b4 + 1] = e1; sk[b4 + 2] = e2; sk[b4 + 3] = e3;
        __syncthreads();
    }
    float4 box[2];
    int val[2];
#pragma unroll
    for (int q = 0; q < 2; q++) {
        int e = 2 * tid + q;
        val[q] = 0;
        box[q] = make_float4(0.f, 0.f, 0.f, 0.f);
        if (e < PRE) {
            unsigned idx = ~(unsigned)(sk[e] & 0xFFFFFFFFULL);
            const float* a = anchors + ((size_t)b * NN + idx) * 4;
            const float* r = reg + ((size_t)b * NN + idx) * 4;
            float a0 = a[0], a1 = a[1], a2 = a[2], a3 = a[3];
            float dx = r[0], dy = r[1], dw = r[2], dh = r[3];
            float aw = a2 - a0, ah = a3 - a1;
            float acx = a0 + 0.5f * aw, acy = a1 + 0.5f * ah;
            float pcx = dx * aw + acx, pcy = dy * ah + acy;
            float pw = expf(dw) * aw, ph = expf(dh) * ah;
            float x1 = pcx - 0.5f * pw, y1 = pcy - 0.5f * ph;
            float x2 = pcx + 0.5f * pw, y2 = pcy + 0.5f * ph;
            x1 = fminf(fmaxf(x1, 0.f), 1333.f);
            y1 = fminf(fmaxf(y1, 0.f), 800.f);
            x2 = fminf(fmaxf(x2, 0.f), 1333.f);
            y2 = fminf(fmaxf(y2, 0.f), 800.f);
            float w = x2 - x1, h = y2 - y1;
            val[q] = (w >= 0.001f && h >= 0.001f) ? 1 : 0;
            box[q] = make_float4(x1, y1, x2, y2);
        }
    }
    int pairsum = val[0] + val[1];
    int v = pairsum;
    for (int o = 1; o < 32; o <<= 1) {
        int t2 = __shfl_up_sync(0xffffffffu, v, o);
        if (lane >= o) v += t2;
    }
    if (lane == 31) swsum[wid] = v;
    __syncthreads();
    if (wid == 0) {
        int x = swsum[lane];
        for (int o = 1; o < 32; o <<= 1) {
            int t2 = __shfl_up_sync(0xffffffffu, x, o);
            if (lane >= o) x += t2;
        }
        swsum[lane] = x;
    }
    __syncthreads();
    int incl = v + (wid ? swsum[wid - 1] : 0);
    int excl = incl - pairsum;
    int nv = swsum[31];
    int ea = 2 * tid, eb = 2 * tid + 1;
    int rank0 = excl;
    int rank1 = excl + val[0];
    int pos0 = val[0] ? rank0 : nv + (ea - rank0);
    int pos1 = val[1] ? rank1 : nv + (eb - rank1);
    if (ea < PRE) {
        g_boxes[b][pos0] = box[0];
        g_area[b][pos0] = (box[0].z - box[0].x) * (box[0].w - box[0].y);
    }
    if (eb < PRE) {
        g_boxes[b][pos1] = box[1];
        g_area[b][pos1] = (box[1].z - box[1].x) * (box[1].w - box[1].y);
    }
    if (tid == 0) g_nvalid[b] = nv;
}

#define C_HI 0.41177000588f   /* (7/17)*(1+1e-5) */
#define C_LO 0.41176177060f   /* (7/17)*(1-1e-5) */

__global__ void __launch_bounds__(256) k_mask(int b0) {
    int b = blockIdx.y + b0;
    int g = threadIdx.x >> 6;
    int t = threadIdx.x & 63;
    int lin = blockIdx.x, rblk = 0;
    for (;;) {
        int cnt = (32 - rblk + 3) >> 2;
        if (lin < cnt) break;
        lin -= cnt;
        rblk++;
    }
    int cblk = rblk + 4 * lin + g;
    bool validc = (cblk < 32);
    __shared__ float4 cbox[4][64];
    __shared__ float carea[4][64];
    if (validc) {
        int j0 = (cblk << 6) + t;
        cbox[g][t] = (j0 < PRE) ? g_boxes[b][j0] : make_float4(-1.f, -1.f, -1.f, -1.f);
        carea[g][t] = (j0 < PRE) ? g_area[b][j0] : 0.f;
    }
    __syncthreads();
    if (!validc) return;
    int i = (rblk << 6) + t;
    if (i >= PRE) return;
    float4 bi = g_boxes[b][i];
    float areai = g_area[b][i];
    float kAhi = C_HI * areai;
    float kAlo = C_LO * areai;
    unsigned blo = 0u, bhi = 0u, alo = 0u, ahi = 0u;
#define IOUB(c, BL, AL, SH) { \
        float4 bj = cbox[g][c]; \
        float aj = carea[g][c]; \
        float w = fmaxf(fminf(bi.z, bj.z) - fmaxf(bi.x, bj.x), 0.f); \
        float h = fminf(bi.w, bj.w) - fmaxf(bi.y, bj.y); \
        float inter = w * h; \
        bool s1 = inter > fmaf(C_HI, aj, kAhi); \
        bool a1 = (!s1) && (inter >= fmaf(C_LO, aj, kAlo)); \
        BL |= ((unsigned)s1) << (SH); \
        AL |= ((unsigned)a1) << (SH); }
    if (cblk == rblk) {
        for (int c = t + 1; c < 64; c++) {
            if (c < 32) { IOUB(c, blo, alo, c) }
            else { IOUB(c, bhi, ahi, c - 32) }
        }
    } else {
#pragma unroll
        for (int c = 0; c < 32; c++) { IOUB(c, blo, alo, c) }
#pragma unroll
        for (int c = 32; c < 64; c++) { IOUB(c, bhi, ahi, c - 32) }
    }
#undef IOUB
    ull bits = ((ull)bhi << 32) | blo;
    ull amb = ((ull)ahi << 32) | alo;
    while (amb) {
        int c = __ffsll(amb) - 1;
        amb &= amb - 1;
        float4 bj = cbox[g][c];
        float w = fmaxf(fminf(bi.z, bj.z) - fmaxf(bi.x, bj.x), 0.f);
        float h = fmaxf(fminf(bi.w, bj.w) - fmaxf(bi.y, bj.y), 0.f);
        float inter = w * h;
        float um = fmaxf((areai + carea[g][c]) - inter, 1e-8f);
        if (__fdiv_rn(inter, um) > 0.7f) bits |= 1ULL << c;
    }
    g_mask[b][i][cblk] = bits;
}

__global__ void __launch_bounds__(256) k_scan(float4* __restrict__ out, int b0) {
    __shared__ ull ring[4][16][32];
    __shared__ int sel[POST];
    __shared__ int skc;
    int b = blockIdx.x + b0;
    int tid = threadIdx.x;
    if (tid < 32) {
        int lane = tid;
        int nv = g_nvalid[b];
        int lo = lane * 64;
        ull rem;
        if (nv <= lo) rem = ~0ULL;
        else if (nv >= lo + 64) rem = 0ULL;
        else rem = (~0ULL) << (nv - lo);
        for (int nb = 0; nb < 3; nb++) {
#pragma unroll
            for (int q = 0; q < 16; q++)
                CP8(smaddr(&ring[nb][q][lane]), &g_mask[b][nb * 16 + q][lane]);
            CPCOMMIT();
        }
        int limit = (PRE < nv) ? PRE : nv;
        int kc = 0, w = 0;
        ull r = 0ULL;
        for (int bt = 0; bt < PRE / 16; bt++) {
            CPWAIT2();
            __syncwarp();
            int base = bt * 16;
            if (base >= limit) break;
            if ((base & 63) == 0) {
                w = base >> 6;
                r = __shfl_sync(0xffffffffu, rem, w);
            }
            ull m[16];
            unsigned keptm = 0;
            if (lane == 0) {
#pragma unroll
                for (int q = 0; q < 16; q++) m[q] = ring[bt & 3][q][w];
                int off = base & 63;
#pragma unroll
                for (int q = 0; q < 16; q++) {
                    int row = base + q;
                    bool keep = (row < limit) && !((r >> (off + q)) & 1ULL);
                    if (keep) {
                        if (kc < POST) sel[kc] = row;
                        kc++;
                        keptm |= 1u << q;
                        r |= m[q];
                    }
                }
            }
            keptm = __shfl_sync(0xffffffffu, keptm, 0);
            ull acc = 0ULL;
#pragma unroll
            for (int q = 0; q < 16; q++)
                if ((keptm >> q) & 1u) acc |= ring[bt & 3][q][lane];
            if (lane >= w) rem |= acc;
            kc = __shfl_sync(0xffffffffu, kc, 0);
            if (kc >= POST) break;
            int nb = bt + 3;
            if (nb < PRE / 16) {
#pragma unroll
                for (int q = 0; q < 16; q++)
                    CP8(smaddr(&ring[nb & 3][q][lane]), &g_mask[b][nb * 16 + q][lane]);
            }
            CPCOMMIT();
        }
        CPWAITALL();
        if (lane == 0) skc = (kc < POST) ? kc : POST;
    }
    __syncthreads();
    int kc = skc;
    for (int k = tid; k < POST; k += blockDim.x) {
        float4 v = make_float4(0.f, 0.f, 0.f, 0.f);
        if (k < kc) v = g_boxes[b][sel[k]];
        out[(size_t)b * POST + k] = v;
    }
    // restore state for next graph replay
    for (int k = tid; k < 2048; k += blockDim.x) g_hist[b][k] = 0u;
    if (tid == 0) g_ccount[b] = 0u;
}

// Streams/events created once at module load (before harness mem checkpoints;
// no device-memory allocation in kernel_launch itself).
namespace {
struct StreamPack {
    cudaStream_t s[GRP];
    cudaEvent_t root;
    cudaEvent_t done[GRP];
    StreamPack() {
        for (int i = 0; i < GRP; i++)
            cudaStreamCreateWithFlags(&s[i], cudaStreamNonBlocking);
        cudaEventCreateWithFlags(&root, cudaEventDisableTiming);
        for (int i = 0; i < GRP; i++)
            cudaEventCreateWithFlags(&done[i], cudaEventDisableTiming);
    }
};
StreamPack g_sp;
}

extern "C" void kernel_launch(void* const* d_in, const int* in_sizes, int n_in,
                              void* d_out, int out_size) {
    const float* cls = (const float*)d_in[0];
    const float* reg = (const float*)d_in[1];
    const float* anchors = (const float*)d_in[2];
    float4* out = (float4*)d_out;

    cudaEventRecord(g_sp.root, 0);
    for (int g = 0; g < GRP; g++) {
        cudaStream_t st = g_sp.s[g];
        cudaStreamWaitEvent(st, g_sp.root, 0);
        int b0 = g * BPG;
        k_hist<<<dim3(NBLK, BPG), 256, 0, st>>>(cls, b0);
        k_compact<<<dim3(NBLK, BPG), 256, 0, st>>>(cls, b0);
        k_sortdecode<<<BPG, 1024, 0, st>>>(reg, anchors, b0);
        k_mask<<<dim3(144, BPG), 256, 0, st>>>(b0);
        k_scan<<<BPG, 256, 0, st>>>(out, b0);
        cudaEventRecord(g_sp.done[g], st);
    }
    for (int g = 0; g < GRP; g++)
        cudaStreamWaitEvent((cudaStream_t)0, g_sp.done[g], 0);
}